// round 15
// baseline (speedup 1.0000x reference)
#include <cuda_runtime.h>
#include <cuda_fp16.h>

#define Nn 50000
#define Ee 800000
#define Hh 64
#define Ll 4
#define Gg 500
#define Cc 10
#define BN_EPS 1e-5f
#define NCHUNK 49   // ceil((Nn+1)/1024)

// ---------------- device scratch ----------------
__device__ __align__(16) __half2 g_hx[(size_t)4 * Nn * 32];  // fp16 h mirrors: slot0=x, slot l+1=h_l
__device__ __align__(16) __half2 g_zh[(size_t)Nn * 32];      // gathered z, fp16
__device__ __align__(16) __half g_W1h[Ll * Hh * Hh];         // BN-folded W1, fp16, TRANSPOSED [c][k]
__device__ __align__(16) __half g_W2h[Ll * Hh * Hh];         // BN-folded W2, fp16, TRANSPOSED [c][k]
__device__ __align__(16) float g_c1[Ll * Hh];
__device__ __align__(16) float g_c2[Ll * Hh];
__device__ __align__(16) float g_pool[Gg * Ll * Hh];   // zeroed inside fill_k
// CSR by destination
__device__ int g_cnt[Nn + 1];       // zeroed by fill_k after use
__device__ int g_indptr[Nn + 1];
__device__ int g_cursor[Nn];
__device__ int g_idx[Ee];
__device__ int g_bsum[NCHUNK];
__device__ int g_ready[NCHUNK];     // zeroed by fill_k after use

// ---------------- mma / ldmatrix helpers ----------------
__device__ __forceinline__ void ldsm4(unsigned &r0, unsigned &r1, unsigned &r2, unsigned &r3,
                                      unsigned addr) {
    asm volatile("ldmatrix.sync.aligned.m8n8.x4.shared.b16 {%0,%1,%2,%3}, [%4];"
                 : "=r"(r0), "=r"(r1), "=r"(r2), "=r"(r3) : "r"(addr));
}
__device__ __forceinline__ void mma16816(float4 &d, unsigned a0, unsigned a1, unsigned a2,
                                         unsigned a3, unsigned b0, unsigned b1) {
    asm volatile("mma.sync.aligned.m16n8k16.row.col.f32.f16.f16.f32 "
                 "{%0,%1,%2,%3}, {%4,%5,%6,%7}, {%8,%9}, {%0,%1,%2,%3};"
                 : "+f"(d.x), "+f"(d.y), "+f"(d.z), "+f"(d.w)
                 : "r"(a0), "r"(a1), "r"(a2), "r"(a3), "r"(b0), "r"(b1));
}

// ---------------- hist + BN fold (fp16 transposed weights) ----------------
__global__ void histfold_k(const int* __restrict__ ei,
                           const float* __restrict__ W1, const float* __restrict__ b1,
                           const float* __restrict__ g1, const float* __restrict__ be1,
                           const float* __restrict__ m1, const float* __restrict__ v1,
                           const float* __restrict__ W2, const float* __restrict__ b2,
                           const float* __restrict__ g2, const float* __restrict__ be2,
                           const float* __restrict__ m2, const float* __restrict__ v2) {
    int t = blockIdx.x * blockDim.x + threadIdx.x;
    if (t < Ll * Hh * Hh) {
        int j = t & 63;
        int k = (t >> 6) & 63;
        int l = t >> 12;
        int lj = l * Hh + j;
        float s1 = g1[lj] * rsqrtf(v1[lj] + BN_EPS);
        float s2 = g2[lj] * rsqrtf(v2[lj] + BN_EPS);
        g_W1h[(l << 12) + (j << 6) + k] = __float2half(W1[t] * s1);
        g_W2h[(l << 12) + (j << 6) + k] = __float2half(W2[t] * s2);
        if (k == 0) {
            g_c1[lj] = b1[lj] * s1 + be1[lj] - m1[lj] * s1;
            g_c2[lj] = b2[lj] * s2 + be2[lj] - m2[lj] * s2;
        }
    }
    if (t < Ee) atomicAdd(g_cnt + __ldg(ei + Ee + t), 1);
}

// ---------------- single-kernel scan (decoupled lookback) ----------------
__global__ void scan_k() {
    __shared__ int wsum[32];
    __shared__ int chunk_off;
    int b = blockIdx.x;
    int t = threadIdx.x;
    int lane = t & 31;
    int wid = t >> 5;
    int idx = b * 1024 + t;
    int v = (idx < Nn + 1) ? g_cnt[idx] : 0;

    int incl = v;
    #pragma unroll
    for (int off = 1; off < 32; off <<= 1) {
        int n = __shfl_up_sync(0xffffffffu, incl, off);
        if (lane >= off) incl += n;
    }
    if (lane == 31) wsum[wid] = incl;
    __syncthreads();
    if (t < 32) {
        int s = wsum[t];
        #pragma unroll
        for (int off = 1; off < 32; off <<= 1) {
            int n = __shfl_up_sync(0xffffffffu, s, off);
            if (t >= off) s += n;
        }
        wsum[t] = s;
    }
    __syncthreads();

    if (t == 0) {
        g_bsum[b] = wsum[31];
        __threadfence();
        atomicExch(g_ready + b, 1);
    }
    if (t < b) {
        while (atomicAdd(g_ready + t, 0) == 0) {}
    }
    __syncthreads();
    if (t == 0) {
        int off = 0;
        for (int i = 0; i < b; i++) off += g_bsum[i];
        chunk_off = off;
    }
    __syncthreads();

    int excl = incl - v + (wid > 0 ? wsum[wid - 1] : 0) + chunk_off;
    if (idx < Nn + 1) {
        g_indptr[idx] = excl;
        if (idx < Nn) g_cursor[idx] = excl;
    }
}

// ---------------- fill CSR + x->fp16 mirror + zero pool + restore zeros ----------------
__global__ void fill_k(const int* __restrict__ ei, const float* __restrict__ x) {
    int e = blockIdx.x * blockDim.x + threadIdx.x;
    if (e < Nn + 1) g_cnt[e] = 0;
    if (e < NCHUNK) g_ready[e] = 0;
    if (e < Gg * Ll * Hh / 4)
        reinterpret_cast<float4*>(g_pool)[e] = make_float4(0.f, 0.f, 0.f, 0.f);
    if (e >= Ee) return;
    {   // fp16 mirror of x: Ee == Nn*Hh/4 float4 chunks exactly
        float4 v = *reinterpret_cast<const float4*>(x + (size_t)e * 4);
        g_hx[(size_t)e * 2]     = __floats2half2_rn(v.x, v.y);
        g_hx[(size_t)e * 2 + 1] = __floats2half2_rn(v.z, v.w);
    }
    int s = __ldg(ei + e);
    int d = __ldg(ei + Ee + e);
    int pos = atomicAdd(g_cursor + d, 1);
    g_idx[pos] = s;
}

// ---------------- gather: uint4 lanes (8 lanes/node, 4 nodes/warp), 8-deep ----------------
__device__ __forceinline__ void cvt_acc8(float* a, uint4 v) {
    float2 p0 = __half22float2(*reinterpret_cast<__half2*>(&v.x));
    float2 p1 = __half22float2(*reinterpret_cast<__half2*>(&v.y));
    float2 p2 = __half22float2(*reinterpret_cast<__half2*>(&v.z));
    float2 p3 = __half22float2(*reinterpret_cast<__half2*>(&v.w));
    a[0] += p0.x; a[1] += p0.y; a[2] += p1.x; a[3] += p1.y;
    a[4] += p2.x; a[5] += p2.y; a[6] += p3.x; a[7] += p3.y;
}

__global__ void __launch_bounds__(256) gather_k(const __half2* __restrict__ hx) {
    int lane = threadIdx.x & 31;
    int wid = threadIdx.x >> 5;
    int nd = lane >> 3;      // node within warp (0..3)
    int hl = lane & 7;       // uint4 column (0..7): halves 8hl..8hl+7
    int gr = blockIdx.x * 32 + wid * 4 + nd;
    if (gr >= Nn) return;

    const uint4* hp = reinterpret_cast<const uint4*>(hx);   // row = 8 uint4 (128B)
    float a[8] = {0.f, 0.f, 0.f, 0.f, 0.f, 0.f, 0.f, 0.f};
    cvt_acc8(a, __ldg(hp + (size_t)gr * 8 + hl));           // self

    int e = __ldg(g_indptr + gr);
    int end = __ldg(g_indptr + gr + 1);

    for (; e + 8 <= end; e += 8) {
        int s0 = __ldg(g_idx + e);
        int s1 = __ldg(g_idx + e + 1);
        int s2 = __ldg(g_idx + e + 2);
        int s3 = __ldg(g_idx + e + 3);
        int s4 = __ldg(g_idx + e + 4);
        int s5 = __ldg(g_idx + e + 5);
        int s6 = __ldg(g_idx + e + 6);
        int s7 = __ldg(g_idx + e + 7);
        uint4 v0 = __ldg(hp + (size_t)s0 * 8 + hl);
        uint4 v1 = __ldg(hp + (size_t)s1 * 8 + hl);
        uint4 v2 = __ldg(hp + (size_t)s2 * 8 + hl);
        uint4 v3 = __ldg(hp + (size_t)s3 * 8 + hl);
        uint4 v4 = __ldg(hp + (size_t)s4 * 8 + hl);
        uint4 v5 = __ldg(hp + (size_t)s5 * 8 + hl);
        uint4 v6 = __ldg(hp + (size_t)s6 * 8 + hl);
        uint4 v7 = __ldg(hp + (size_t)s7 * 8 + hl);
        cvt_acc8(a, v0); cvt_acc8(a, v1); cvt_acc8(a, v2); cvt_acc8(a, v3);
        cvt_acc8(a, v4); cvt_acc8(a, v5); cvt_acc8(a, v6); cvt_acc8(a, v7);
    }
    for (; e < end; e++) {
        int s = __ldg(g_idx + e);
        cvt_acc8(a, __ldg(hp + (size_t)s * 8 + hl));
    }

    uint4 outv;
    __half2 o0 = __floats2half2_rn(a[0], a[1]);
    __half2 o1 = __floats2half2_rn(a[2], a[3]);
    __half2 o2 = __floats2half2_rn(a[4], a[5]);
    __half2 o3 = __floats2half2_rn(a[6], a[7]);
    outv.x = *reinterpret_cast<unsigned*>(&o0);
    outv.y = *reinterpret_cast<unsigned*>(&o1);
    outv.z = *reinterpret_cast<unsigned*>(&o2);
    outv.w = *reinterpret_cast<unsigned*>(&o3);
    reinterpret_cast<uint4*>(g_zh)[(size_t)gr * 8 + hl] = outv;
}

// ---------------- GIN MLP via HMMA: 256 thr, 128-row tile, warp = 16 rows ----------------
#define SZP 72   // smem row stride in halves
__global__ void __launch_bounds__(256, 3) mlp_k(__half2* __restrict__ hxout,
                                                const int* __restrict__ batch,
                                                int layer, int write_h) {
    __shared__ __align__(16) __half sZ[128 * SZP];
    __shared__ __align__(16) __half sW1[64 * SZP];
    __shared__ __align__(16) __half sW2[64 * SZP];

    int tid = threadIdx.x;
    int row0 = blockIdx.x * 128;

    const uint4* zg = reinterpret_cast<const uint4*>(g_zh);
    for (int i = tid; i < 1024; i += 256) {
        int r = i >> 3;
        int c = i & 7;
        int gr = row0 + r;
        uint4 v = make_uint4(0u, 0u, 0u, 0u);
        if (gr < Nn) v = __ldg(zg + (size_t)gr * 8 + c);
        *reinterpret_cast<uint4*>(sZ + r * SZP + c * 8) = v;
    }
    {
        const uint4* w1 = reinterpret_cast<const uint4*>(g_W1h + layer * 4096);
        const uint4* w2 = reinterpret_cast<const uint4*>(g_W2h + layer * 4096);
        for (int i = tid; i < 512; i += 256) {
            int r = i >> 3;
            int c = i & 7;
            *reinterpret_cast<uint4*>(sW1 + r * SZP + c * 8) = __ldg(w1 + i);
            *reinterpret_cast<uint4*>(sW2 + r * SZP + c * 8) = __ldg(w2 + i);
        }
    }
    __syncthreads();

    int warp = tid >> 5;
    int lane = tid & 31;
    int m0 = warp * 16;

    unsigned zbase, w1base, w2base;
    zbase  = (unsigned)__cvta_generic_to_shared(sZ);
    w1base = (unsigned)__cvta_generic_to_shared(sW1);
    w2base = (unsigned)__cvta_generic_to_shared(sW2);

    int ar = lane & 15;
    int akoff = (lane >> 4) * 8;
    int bnrow = ((lane >> 4) & 1) * 8 + (lane & 7);
    int bkoff = ((lane >> 3) & 1) * 8;

    float4 acc[8];
    #pragma unroll
    for (int n = 0; n < 8; n++) acc[n] = make_float4(0.f, 0.f, 0.f, 0.f);

    // GEMM1
    #pragma unroll
    for (int k0 = 0; k0 < 64; k0 += 16) {
        unsigned a0, a1, a2, a3;
        ldsm4(a0, a1, a2, a3, zbase + ((m0 + ar) * SZP + k0 + akoff) * 2);
        #pragma unroll
        for (int nt = 0; nt < 8; nt += 2) {
            unsigned b0, b1, b2, b3;
            ldsm4(b0, b1, b2, b3, w1base + ((nt * 8 + bnrow) * SZP + k0 + bkoff) * 2);
            mma16816(acc[nt],     a0, a1, a2, a3, b0, b1);
            mma16816(acc[nt + 1], a0, a1, a2, a3, b2, b3);
        }
    }

    __syncwarp();
    {
        int r1 = m0 + (lane >> 2);
        int r2 = r1 + 8;
        #pragma unroll
        for (int nt = 0; nt < 8; nt++) {
            int c = nt * 8 + (lane & 3) * 2;
            float2 bv = *reinterpret_cast<const float2*>(g_c1 + layer * Hh + c);
            __half2 h1 = __floats2half2_rn(fmaxf(acc[nt].x + bv.x, 0.f),
                                           fmaxf(acc[nt].y + bv.y, 0.f));
            __half2 h2 = __floats2half2_rn(fmaxf(acc[nt].z + bv.x, 0.f),
                                           fmaxf(acc[nt].w + bv.y, 0.f));
            *reinterpret_cast<__half2*>(sZ + r1 * SZP + c) = h1;
            *reinterpret_cast<__half2*>(sZ + r2 * SZP + c) = h2;
        }
    }
    __syncwarp();

    #pragma unroll
    for (int n = 0; n < 8; n++) acc[n] = make_float4(0.f, 0.f, 0.f, 0.f);

    // GEMM2
    #pragma unroll
    for (int k0 = 0; k0 < 64; k0 += 16) {
        unsigned a0, a1, a2, a3;
        ldsm4(a0, a1, a2, a3, zbase + ((m0 + ar) * SZP + k0 + akoff) * 2);
        #pragma unroll
        for (int nt = 0; nt < 8; nt += 2) {
            unsigned b0, b1, b2, b3;
            ldsm4(b0, b1, b2, b3, w2base + ((nt * 8 + bnrow) * SZP + k0 + bkoff) * 2);
            mma16816(acc[nt],     a0, a1, a2, a3, b0, b1);
            mma16816(acc[nt + 1], a0, a1, a2, a3, b2, b3);
        }
    }

    {
        int r1 = m0 + (lane >> 2);
        int r2 = r1 + 8;
        int gr1 = row0 + r1;
        int gr2 = row0 + r2;
        int b1g = (gr1 < Nn) ? __ldg(batch + gr1) : 0;
        int b2g = (gr2 < Nn) ? __ldg(batch + gr2) : 0;
        #pragma unroll
        for (int nt = 0; nt < 8; nt++) {
            int c = nt * 8 + (lane & 3) * 2;
            float2 bv = *reinterpret_cast<const float2*>(g_c2 + layer * Hh + c);
            float y0 = fmaxf(acc[nt].x + bv.x, 0.f);
            float y1v = fmaxf(acc[nt].y + bv.y, 0.f);
            float y2v = fmaxf(acc[nt].z + bv.x, 0.f);
            float y3 = fmaxf(acc[nt].w + bv.y, 0.f);
            if (gr1 < Nn) {
                if (write_h)
                    hxout[(size_t)gr1 * 32 + (c >> 1)] = __floats2half2_rn(y0, y1v);
                float* pp = g_pool + (size_t)b1g * (Ll * Hh) + layer * Hh + c;
                asm volatile("red.global.add.v2.f32 [%0], {%1,%2};"
                             :: "l"(pp), "f"(y0), "f"(y1v) : "memory");
            }
            if (gr2 < Nn) {
                if (write_h)
                    hxout[(size_t)gr2 * 32 + (c >> 1)] = __floats2half2_rn(y2v, y3);
                float* pp = g_pool + (size_t)b2g * (Ll * Hh) + layer * Hh + c;
                asm volatile("red.global.add.v2.f32 [%0], {%1,%2};"
                             :: "l"(pp), "f"(y2v), "f"(y3) : "memory");
            }
        }
    }
}

// ---------------- head ----------------
__global__ void final_k(const float* __restrict__ W1, const float* __restrict__ b1,
                        const float* __restrict__ W2, const float* __restrict__ b2,
                        float* __restrict__ out) {
    int g = blockIdx.x;
    int j = threadIdx.x;   // 64 threads
    __shared__ float sp[Ll * Hh];
    __shared__ float sh[Hh];
    for (int i = j; i < Ll * Hh; i += 64) sp[i] = g_pool[(size_t)g * (Ll * Hh) + i];
    __syncthreads();
    float a = b1[j];
    #pragma unroll 8
    for (int k = 0; k < Ll * Hh; k++) a = fmaf(sp[k], W1[k * Hh + j], a);
    sh[j] = fmaxf(a, 0.f);
    __syncthreads();
    if (j < Cc) {
        float o = b2[j];
        #pragma unroll
        for (int k = 0; k < Hh; k++) o = fmaf(sh[k], W2[k * Cc + j], o);
        out[g * Cc + j] = o;
    }
}

// ---------------- launch (#4 = gather L0, profiled) ----------------
extern "C" void kernel_launch(void* const* d_in, const int* in_sizes, int n_in,
                              void* d_out, int out_size) {
    const float* x     = (const float*)d_in[0];
    const int*   ei    = (const int*)d_in[1];
    const int*   batch = (const int*)d_in[2];
    const float* cW1 = (const float*)d_in[3];
    const float* cb1 = (const float*)d_in[4];
    const float* g1  = (const float*)d_in[5];
    const float* be1 = (const float*)d_in[6];
    const float* m1  = (const float*)d_in[7];
    const float* v1  = (const float*)d_in[8];
    const float* cW2 = (const float*)d_in[9];
    const float* cb2 = (const float*)d_in[10];
    const float* g2  = (const float*)d_in[11];
    const float* be2 = (const float*)d_in[12];
    const float* m2  = (const float*)d_in[13];
    const float* v2  = (const float*)d_in[14];
    const float* l1W = (const float*)d_in[15];
    const float* l1b = (const float*)d_in[16];
    const float* l2W = (const float*)d_in[17];
    const float* l2b = (const float*)d_in[18];
    float* out = (float*)d_out;

    histfold_k<<<(Ee + 255) / 256, 256>>>(ei, cW1, cb1, g1, be1, m1, v1,
                                          cW2, cb2, g2, be2, m2, v2);   // 1
    scan_k<<<NCHUNK, 1024>>>();                                         // 2
    fill_k<<<(Ee + 255) / 256, 256>>>(ei, x);                           // 3

    __half2* hxbase;
    cudaGetSymbolAddress((void**)&hxbase, g_hx);

    for (int l = 0; l < Ll; l++) {
        gather_k<<<(Nn + 31) / 32, 256>>>(hxbase + (size_t)l * Nn * 32);  // 4,6,8,10
        __half2* hxout = hxbase + (size_t)(l + 1) * Nn * 32;
        mlp_k<<<(Nn + 127) / 128, 256>>>(hxout, batch, l, l < Ll - 1 ? 1 : 0); // 5,7,9,11
    }
    final_k<<<Gg, 64>>>(l1W, l1b, l2W, l2b, out);
}

// round 16
// speedup vs baseline: 1.0478x; 1.0478x over previous
#include <cuda_runtime.h>
#include <cuda_fp16.h>

#define Nn 50000
#define Ee 800000
#define Hh 64
#define Ll 4
#define Gg 500
#define Cc 10
#define BN_EPS 1e-5f
#define NCHUNK 49   // ceil((Nn+1)/1024)

// ---------------- device scratch ----------------
__device__ __align__(16) __half2 g_hx[(size_t)4 * Nn * 32];  // fp16 h mirrors: slot0=x, slot l+1=h_l
__device__ __align__(16) __half2 g_zh[(size_t)Nn * 32];      // gathered z, fp16
__device__ __align__(16) __half g_W1h[Ll * Hh * Hh];         // BN-folded W1, fp16, TRANSPOSED [c][k]
__device__ __align__(16) __half g_W2h[Ll * Hh * Hh];         // BN-folded W2, fp16, TRANSPOSED [c][k]
__device__ __align__(16) float g_c1[Ll * Hh];
__device__ __align__(16) float g_c2[Ll * Hh];
__device__ __align__(16) float g_pool[Gg * Ll * Hh];   // zeroed inside fill_k
// CSR by destination
__device__ int g_cnt[Nn + 1];       // zeroed by fill_k after use
__device__ int g_indptr[Nn + 1];
__device__ int g_cursor[Nn];
__device__ int g_idx[Ee];
__device__ int g_bsum[NCHUNK];
__device__ int g_ready[NCHUNK];     // zeroed by fill_k after use

// ---------------- mma / ldmatrix helpers ----------------
__device__ __forceinline__ void ldsm4(unsigned &r0, unsigned &r1, unsigned &r2, unsigned &r3,
                                      unsigned addr) {
    asm volatile("ldmatrix.sync.aligned.m8n8.x4.shared.b16 {%0,%1,%2,%3}, [%4];"
                 : "=r"(r0), "=r"(r1), "=r"(r2), "=r"(r3) : "r"(addr));
}
__device__ __forceinline__ void mma16816(float4 &d, unsigned a0, unsigned a1, unsigned a2,
                                         unsigned a3, unsigned b0, unsigned b1) {
    asm volatile("mma.sync.aligned.m16n8k16.row.col.f32.f16.f16.f32 "
                 "{%0,%1,%2,%3}, {%4,%5,%6,%7}, {%8,%9}, {%0,%1,%2,%3};"
                 : "+f"(d.x), "+f"(d.y), "+f"(d.z), "+f"(d.w)
                 : "r"(a0), "r"(a1), "r"(a2), "r"(a3), "r"(b0), "r"(b1));
}

// ---------------- hist + BN fold (fp16 transposed weights) ----------------
__global__ void histfold_k(const int* __restrict__ ei,
                           const float* __restrict__ W1, const float* __restrict__ b1,
                           const float* __restrict__ g1, const float* __restrict__ be1,
                           const float* __restrict__ m1, const float* __restrict__ v1,
                           const float* __restrict__ W2, const float* __restrict__ b2,
                           const float* __restrict__ g2, const float* __restrict__ be2,
                           const float* __restrict__ m2, const float* __restrict__ v2) {
    int t = blockIdx.x * blockDim.x + threadIdx.x;
    if (t < Ll * Hh * Hh) {
        int j = t & 63;
        int k = (t >> 6) & 63;
        int l = t >> 12;
        int lj = l * Hh + j;
        float s1 = g1[lj] * rsqrtf(v1[lj] + BN_EPS);
        float s2 = g2[lj] * rsqrtf(v2[lj] + BN_EPS);
        g_W1h[(l << 12) + (j << 6) + k] = __float2half(W1[t] * s1);
        g_W2h[(l << 12) + (j << 6) + k] = __float2half(W2[t] * s2);
        if (k == 0) {
            g_c1[lj] = b1[lj] * s1 + be1[lj] - m1[lj] * s1;
            g_c2[lj] = b2[lj] * s2 + be2[lj] - m2[lj] * s2;
        }
    }
    if (t < Ee) atomicAdd(g_cnt + __ldg(ei + Ee + t), 1);
}

// ---------------- single-kernel scan (decoupled lookback) ----------------
__global__ void scan_k() {
    __shared__ int wsum[32];
    __shared__ int chunk_off;
    int b = blockIdx.x;
    int t = threadIdx.x;
    int lane = t & 31;
    int wid = t >> 5;
    int idx = b * 1024 + t;
    int v = (idx < Nn + 1) ? g_cnt[idx] : 0;

    int incl = v;
    #pragma unroll
    for (int off = 1; off < 32; off <<= 1) {
        int n = __shfl_up_sync(0xffffffffu, incl, off);
        if (lane >= off) incl += n;
    }
    if (lane == 31) wsum[wid] = incl;
    __syncthreads();
    if (t < 32) {
        int s = wsum[t];
        #pragma unroll
        for (int off = 1; off < 32; off <<= 1) {
            int n = __shfl_up_sync(0xffffffffu, s, off);
            if (t >= off) s += n;
        }
        wsum[t] = s;
    }
    __syncthreads();

    if (t == 0) {
        g_bsum[b] = wsum[31];
        __threadfence();
        atomicExch(g_ready + b, 1);
    }
    if (t < b) {
        while (atomicAdd(g_ready + t, 0) == 0) {}
    }
    __syncthreads();
    if (t == 0) {
        int off = 0;
        for (int i = 0; i < b; i++) off += g_bsum[i];
        chunk_off = off;
    }
    __syncthreads();

    int excl = incl - v + (wid > 0 ? wsum[wid - 1] : 0) + chunk_off;
    if (idx < Nn + 1) {
        g_indptr[idx] = excl;
        if (idx < Nn) g_cursor[idx] = excl;
    }
}

// ---------------- fill CSR + x->fp16 mirror + zero pool + restore zeros ----------------
__global__ void fill_k(const int* __restrict__ ei, const float* __restrict__ x) {
    int e = blockIdx.x * blockDim.x + threadIdx.x;
    if (e < Nn + 1) g_cnt[e] = 0;
    if (e < NCHUNK) g_ready[e] = 0;
    if (e < Gg * Ll * Hh / 4)
        reinterpret_cast<float4*>(g_pool)[e] = make_float4(0.f, 0.f, 0.f, 0.f);
    if (e >= Ee) return;
    {   // fp16 mirror of x: Ee == Nn*Hh/4 float4 chunks exactly
        float4 v = *reinterpret_cast<const float4*>(x + (size_t)e * 4);
        g_hx[(size_t)e * 2]     = __floats2half2_rn(v.x, v.y);
        g_hx[(size_t)e * 2 + 1] = __floats2half2_rn(v.z, v.w);
    }
    int s = __ldg(ei + e);
    int d = __ldg(ei + Ee + e);
    int pos = atomicAdd(g_cursor + d, 1);
    g_idx[pos] = s;
}

// ---------------- gather: uint4 lanes (8 lanes/node), fp16 pairwise + fp32 accum --------
__device__ __forceinline__ void cvt_acc8(float* a, uint4 v) {
    float2 p0 = __half22float2(*reinterpret_cast<__half2*>(&v.x));
    float2 p1 = __half22float2(*reinterpret_cast<__half2*>(&v.y));
    float2 p2 = __half22float2(*reinterpret_cast<__half2*>(&v.z));
    float2 p3 = __half22float2(*reinterpret_cast<__half2*>(&v.w));
    a[0] += p0.x; a[1] += p0.y; a[2] += p1.x; a[3] += p1.y;
    a[4] += p2.x; a[5] += p2.y; a[6] += p3.x; a[7] += p3.y;
}
__device__ __forceinline__ uint4 hadd4(uint4 a, uint4 b) {
    uint4 r;
    __half2 r0 = __hadd2(*reinterpret_cast<__half2*>(&a.x), *reinterpret_cast<__half2*>(&b.x));
    __half2 r1 = __hadd2(*reinterpret_cast<__half2*>(&a.y), *reinterpret_cast<__half2*>(&b.y));
    __half2 r2 = __hadd2(*reinterpret_cast<__half2*>(&a.z), *reinterpret_cast<__half2*>(&b.z));
    __half2 r3 = __hadd2(*reinterpret_cast<__half2*>(&a.w), *reinterpret_cast<__half2*>(&b.w));
    r.x = *reinterpret_cast<unsigned*>(&r0);
    r.y = *reinterpret_cast<unsigned*>(&r1);
    r.z = *reinterpret_cast<unsigned*>(&r2);
    r.w = *reinterpret_cast<unsigned*>(&r3);
    return r;
}

__global__ void __launch_bounds__(256) gather_k(const __half2* __restrict__ hx) {
    int lane = threadIdx.x & 31;
    int wid = threadIdx.x >> 5;
    int nd = lane >> 3;      // node within warp (0..3)
    int hl = lane & 7;       // uint4 column (0..7)
    int gr = blockIdx.x * 32 + wid * 4 + nd;
    if (gr >= Nn) return;

    const uint4* hp = reinterpret_cast<const uint4*>(hx);   // row = 8 uint4 (128B)
    float a[8] = {0.f, 0.f, 0.f, 0.f, 0.f, 0.f, 0.f, 0.f};
    cvt_acc8(a, __ldg(hp + (size_t)gr * 8 + hl));           // self (exact cvt, fp32 add)

    int e = __ldg(g_indptr + gr);
    int end = __ldg(g_indptr + gr + 1);

    for (; e + 8 <= end; e += 8) {
        int s0 = __ldg(g_idx + e);
        int s1 = __ldg(g_idx + e + 1);
        int s2 = __ldg(g_idx + e + 2);
        int s3 = __ldg(g_idx + e + 3);
        int s4 = __ldg(g_idx + e + 4);
        int s5 = __ldg(g_idx + e + 5);
        int s6 = __ldg(g_idx + e + 6);
        int s7 = __ldg(g_idx + e + 7);
        uint4 v0 = __ldg(hp + (size_t)s0 * 8 + hl);
        uint4 v1 = __ldg(hp + (size_t)s1 * 8 + hl);
        uint4 v2 = __ldg(hp + (size_t)s2 * 8 + hl);
        uint4 v3 = __ldg(hp + (size_t)s3 * 8 + hl);
        uint4 v4 = __ldg(hp + (size_t)s4 * 8 + hl);
        uint4 v5 = __ldg(hp + (size_t)s5 * 8 + hl);
        uint4 v6 = __ldg(hp + (size_t)s6 * 8 + hl);
        uint4 v7 = __ldg(hp + (size_t)s7 * 8 + hl);
        // one level of fp16 pairwise adds (full-rate HADD2), then fp32 accumulate
        cvt_acc8(a, hadd4(v0, v1));
        cvt_acc8(a, hadd4(v2, v3));
        cvt_acc8(a, hadd4(v4, v5));
        cvt_acc8(a, hadd4(v6, v7));
    }
    for (; e + 2 <= end; e += 2) {
        int s0 = __ldg(g_idx + e);
        int s1 = __ldg(g_idx + e + 1);
        uint4 v0 = __ldg(hp + (size_t)s0 * 8 + hl);
        uint4 v1 = __ldg(hp + (size_t)s1 * 8 + hl);
        cvt_acc8(a, hadd4(v0, v1));
    }
    if (e < end) {
        int s = __ldg(g_idx + e);
        cvt_acc8(a, __ldg(hp + (size_t)s * 8 + hl));
    }

    uint4 outv;
    __half2 o0 = __floats2half2_rn(a[0], a[1]);
    __half2 o1 = __floats2half2_rn(a[2], a[3]);
    __half2 o2 = __floats2half2_rn(a[4], a[5]);
    __half2 o3 = __floats2half2_rn(a[6], a[7]);
    outv.x = *reinterpret_cast<unsigned*>(&o0);
    outv.y = *reinterpret_cast<unsigned*>(&o1);
    outv.z = *reinterpret_cast<unsigned*>(&o2);
    outv.w = *reinterpret_cast<unsigned*>(&o3);
    reinterpret_cast<uint4*>(g_zh)[(size_t)gr * 8 + hl] = outv;
}

// ---------------- GIN MLP via HMMA: 256 thr, 128-row tile, warp = 16 rows ----------------
#define SZP 72   // smem row stride in halves
__global__ void __launch_bounds__(256, 3) mlp_k(__half2* __restrict__ hxout,
                                                const int* __restrict__ batch,
                                                int layer, int write_h) {
    __shared__ __align__(16) __half sZ[128 * SZP];
    __shared__ __align__(16) __half sW1[64 * SZP];
    __shared__ __align__(16) __half sW2[64 * SZP];

    int tid = threadIdx.x;
    int row0 = blockIdx.x * 128;

    const uint4* zg = reinterpret_cast<const uint4*>(g_zh);
    for (int i = tid; i < 1024; i += 256) {
        int r = i >> 3;
        int c = i & 7;
        int gr = row0 + r;
        uint4 v = make_uint4(0u, 0u, 0u, 0u);
        if (gr < Nn) v = __ldg(zg + (size_t)gr * 8 + c);
        *reinterpret_cast<uint4*>(sZ + r * SZP + c * 8) = v;
    }
    {
        const uint4* w1 = reinterpret_cast<const uint4*>(g_W1h + layer * 4096);
        const uint4* w2 = reinterpret_cast<const uint4*>(g_W2h + layer * 4096);
        for (int i = tid; i < 512; i += 256) {
            int r = i >> 3;
            int c = i & 7;
            *reinterpret_cast<uint4*>(sW1 + r * SZP + c * 8) = __ldg(w1 + i);
            *reinterpret_cast<uint4*>(sW2 + r * SZP + c * 8) = __ldg(w2 + i);
        }
    }
    __syncthreads();

    int warp = tid >> 5;
    int lane = tid & 31;
    int m0 = warp * 16;

    unsigned zbase, w1base, w2base;
    zbase  = (unsigned)__cvta_generic_to_shared(sZ);
    w1base = (unsigned)__cvta_generic_to_shared(sW1);
    w2base = (unsigned)__cvta_generic_to_shared(sW2);

    int ar = lane & 15;
    int akoff = (lane >> 4) * 8;
    int bnrow = ((lane >> 4) & 1) * 8 + (lane & 7);
    int bkoff = ((lane >> 3) & 1) * 8;

    float4 acc[8];
    #pragma unroll
    for (int n = 0; n < 8; n++) acc[n] = make_float4(0.f, 0.f, 0.f, 0.f);

    // GEMM1
    #pragma unroll
    for (int k0 = 0; k0 < 64; k0 += 16) {
        unsigned a0, a1, a2, a3;
        ldsm4(a0, a1, a2, a3, zbase + ((m0 + ar) * SZP + k0 + akoff) * 2);
        #pragma unroll
        for (int nt = 0; nt < 8; nt += 2) {
            unsigned b0, b1, b2, b3;
            ldsm4(b0, b1, b2, b3, w1base + ((nt * 8 + bnrow) * SZP + k0 + bkoff) * 2);
            mma16816(acc[nt],     a0, a1, a2, a3, b0, b1);
            mma16816(acc[nt + 1], a0, a1, a2, a3, b2, b3);
        }
    }

    __syncwarp();
    {
        int r1 = m0 + (lane >> 2);
        int r2 = r1 + 8;
        #pragma unroll
        for (int nt = 0; nt < 8; nt++) {
            int c = nt * 8 + (lane & 3) * 2;
            float2 bv = *reinterpret_cast<const float2*>(g_c1 + layer * Hh + c);
            __half2 h1 = __floats2half2_rn(fmaxf(acc[nt].x + bv.x, 0.f),
                                           fmaxf(acc[nt].y + bv.y, 0.f));
            __half2 h2 = __floats2half2_rn(fmaxf(acc[nt].z + bv.x, 0.f),
                                           fmaxf(acc[nt].w + bv.y, 0.f));
            *reinterpret_cast<__half2*>(sZ + r1 * SZP + c) = h1;
            *reinterpret_cast<__half2*>(sZ + r2 * SZP + c) = h2;
        }
    }
    __syncwarp();

    #pragma unroll
    for (int n = 0; n < 8; n++) acc[n] = make_float4(0.f, 0.f, 0.f, 0.f);

    // GEMM2
    #pragma unroll
    for (int k0 = 0; k0 < 64; k0 += 16) {
        unsigned a0, a1, a2, a3;
        ldsm4(a0, a1, a2, a3, zbase + ((m0 + ar) * SZP + k0 + akoff) * 2);
        #pragma unroll
        for (int nt = 0; nt < 8; nt += 2) {
            unsigned b0, b1, b2, b3;
            ldsm4(b0, b1, b2, b3, w2base + ((nt * 8 + bnrow) * SZP + k0 + bkoff) * 2);
            mma16816(acc[nt],     a0, a1, a2, a3, b0, b1);
            mma16816(acc[nt + 1], a0, a1, a2, a3, b2, b3);
        }
    }

    {
        int r1 = m0 + (lane >> 2);
        int r2 = r1 + 8;
        int gr1 = row0 + r1;
        int gr2 = row0 + r2;
        int b1g = (gr1 < Nn) ? __ldg(batch + gr1) : 0;
        int b2g = (gr2 < Nn) ? __ldg(batch + gr2) : 0;
        #pragma unroll
        for (int nt = 0; nt < 8; nt++) {
            int c = nt * 8 + (lane & 3) * 2;
            float2 bv = *reinterpret_cast<const float2*>(g_c2 + layer * Hh + c);
            float y0 = fmaxf(acc[nt].x + bv.x, 0.f);
            float y1v = fmaxf(acc[nt].y + bv.y, 0.f);
            float y2v = fmaxf(acc[nt].z + bv.x, 0.f);
            float y3 = fmaxf(acc[nt].w + bv.y, 0.f);
            if (gr1 < Nn) {
                if (write_h)
                    hxout[(size_t)gr1 * 32 + (c >> 1)] = __floats2half2_rn(y0, y1v);
                float* pp = g_pool + (size_t)b1g * (Ll * Hh) + layer * Hh + c;
                asm volatile("red.global.add.v2.f32 [%0], {%1,%2};"
                             :: "l"(pp), "f"(y0), "f"(y1v) : "memory");
            }
            if (gr2 < Nn) {
                if (write_h)
                    hxout[(size_t)gr2 * 32 + (c >> 1)] = __floats2half2_rn(y2v, y3);
                float* pp = g_pool + (size_t)b2g * (Ll * Hh) + layer * Hh + c;
                asm volatile("red.global.add.v2.f32 [%0], {%1,%2};"
                             :: "l"(pp), "f"(y2v), "f"(y3) : "memory");
            }
        }
    }
}

// ---------------- head ----------------
__global__ void final_k(const float* __restrict__ W1, const float* __restrict__ b1,
                        const float* __restrict__ W2, const float* __restrict__ b2,
                        float* __restrict__ out) {
    int g = blockIdx.x;
    int j = threadIdx.x;   // 64 threads
    __shared__ float sp[Ll * Hh];
    __shared__ float sh[Hh];
    for (int i = j; i < Ll * Hh; i += 64) sp[i] = g_pool[(size_t)g * (Ll * Hh) + i];
    __syncthreads();
    float a = b1[j];
    #pragma unroll 8
    for (int k = 0; k < Ll * Hh; k++) a = fmaf(sp[k], W1[k * Hh + j], a);
    sh[j] = fmaxf(a, 0.f);
    __syncthreads();
    if (j < Cc) {
        float o = b2[j];
        #pragma unroll
        for (int k = 0; k < Hh; k++) o = fmaf(sh[k], W2[k * Cc + j], o);
        out[g * Cc + j] = o;
    }
}

// ---------------- launch (#4 = gather L0, profiled) ----------------
extern "C" void kernel_launch(void* const* d_in, const int* in_sizes, int n_in,
                              void* d_out, int out_size) {
    const float* x     = (const float*)d_in[0];
    const int*   ei    = (const int*)d_in[1];
    const int*   batch = (const int*)d_in[2];
    const float* cW1 = (const float*)d_in[3];
    const float* cb1 = (const float*)d_in[4];
    const float* g1  = (const float*)d_in[5];
    const float* be1 = (const float*)d_in[6];
    const float* m1  = (const float*)d_in[7];
    const float* v1  = (const float*)d_in[8];
    const float* cW2 = (const float*)d_in[9];
    const float* cb2 = (const float*)d_in[10];
    const float* g2  = (const float*)d_in[11];
    const float* be2 = (const float*)d_in[12];
    const float* m2  = (const float*)d_in[13];
    const float* v2  = (const float*)d_in[14];
    const float* l1W = (const float*)d_in[15];
    const float* l1b = (const float*)d_in[16];
    const float* l2W = (const float*)d_in[17];
    const float* l2b = (const float*)d_in[18];
    float* out = (float*)d_out;

    histfold_k<<<(Ee + 255) / 256, 256>>>(ei, cW1, cb1, g1, be1, m1, v1,
                                          cW2, cb2, g2, be2, m2, v2);   // 1
    scan_k<<<NCHUNK, 1024>>>();                                         // 2
    fill_k<<<(Ee + 255) / 256, 256>>>(ei, x);                           // 3

    __half2* hxbase;
    cudaGetSymbolAddress((void**)&hxbase, g_hx);

    for (int l = 0; l < Ll; l++) {
        gather_k<<<(Nn + 31) / 32, 256>>>(hxbase + (size_t)l * Nn * 32);  // 4,6,8,10
        __half2* hxout = hxbase + (size_t)(l + 1) * Nn * 32;
        mlp_k<<<(Nn + 127) / 128, 256>>>(hxout, batch, l, l < Ll - 1 ? 1 : 0); // 5,7,9,11
    }
    final_k<<<Gg, 64>>>(l1W, l1b, l2W, l2b, out);
}